// round 16
// baseline (speedup 1.0000x reference)
#include <cuda_runtime.h>
#include <math.h>

// ---------------- fixed problem constants ----------------
#define U_N   51200
#define I_N   25600
#define E_MAX 1000000
#define NCH   200          // U_N / 256 chunks
#define RS2   68           // padded smem row stride (words) for contrast (tf32)
#define NB_U  50           // U_N / 1024
#define NB_I  25           // I_N / 1024
#define NB_T  75

typedef unsigned long long u64;
typedef unsigned int u32;
typedef unsigned short u16;

// ---------------- device scratch (static, no runtime alloc) ----------------
// g_cntU/g_cntI start zero and are re-zeroed by scanC each call; g_ticket self-resets.
__device__ __align__(256) float g_L1u[U_N * 64];
__device__ __align__(256) float g_L1i[I_N * 64];
__device__ __align__(256) float g_hu [U_N * 64];
__device__ __align__(256) float g_hi [I_N * 64];
__device__ __align__(256) float g_anchor[U_N * 64];
__device__ __align__(256) int g_cntU[U_N];
__device__ __align__(256) int g_cntI[I_N];
__device__ __align__(256) int g_startU[U_N + 1];
__device__ __align__(256) int g_startI[I_N + 1];
__device__ __align__(256) int g_curU[U_N];
__device__ __align__(256) int g_curI[I_N];
__device__ __align__(256) u16 g_adjU[E_MAX];   // per user: neighbor items (<25600 fits u16)
__device__ __align__(256) u16 g_adjI[E_MAX];   // per item: neighbor users (<51200 fits u16)
__device__ int g_bsum[NB_T];
__device__ int g_ticket;
__device__ float g_wa[64];
__device__ float g_v1[64];
__device__ float g_v2[64];
__device__ float g_circ[8 * 64];          // [tap m][d]
__device__ float g_partial[NCH];          // per-chunk contrast partials

// ---------------- CSR: count ----------------
__global__ void count_kernel(const int* __restrict__ src, const int* __restrict__ dst, int E) {
    int e = blockIdx.x * blockDim.x + threadIdx.x;
    if (e >= E) return;
    atomicAdd(&g_cntU[__ldg(src + e)], 1);
    atomicAdd(&g_cntI[__ldg(dst + e)], 1);
}

// ---------------- CSR scan stage A: block-local exclusive scan ----------------
__global__ void __launch_bounds__(1024) scanA_kernel() {
    int b = blockIdx.x;
    int isI = (b >= NB_U);
    const int* c = isI ? g_cntI : g_cntU;
    int* st = isI ? g_startI : g_startU;
    int base = (isI ? (b - NB_U) : b) * 1024;
    int t = threadIdx.x, lane = t & 31, wid = t >> 5;
    __shared__ int ws[32];
    int v = c[base + t];
    int x = v;
#pragma unroll
    for (int o = 1; o < 32; o <<= 1) {
        int y = __shfl_up_sync(~0u, x, o);
        if (lane >= o) x += y;
    }
    if (lane == 31) ws[wid] = x;
    __syncthreads();
    if (wid == 0) {
        int s = ws[lane];
#pragma unroll
        for (int o = 1; o < 32; o <<= 1) {
            int y = __shfl_up_sync(~0u, s, o);
            if (lane >= o) s += y;
        }
        ws[lane] = s;
    }
    __syncthreads();
    int incl = x + (wid ? ws[wid - 1] : 0);
    st[base + t] = incl - v;
    if (t == 1023) g_bsum[b] = incl;
}

// ---------------- CSR scan stage C: segment offsets (from bsum) + cursors + re-zero ----
__global__ void __launch_bounds__(1024) scanC_kernel(int E) {
    __shared__ int sb[NB_T];
    __shared__ int soff;
    int b = blockIdx.x, t = threadIdx.x;
    if (t < NB_T) sb[t] = g_bsum[t];
    __syncthreads();
    int isI = (b >= NB_U);
    int seg0 = isI ? NB_U : 0;
    if (t == 0) {
        int o = 0;
        for (int j = seg0; j < b; j++) o += sb[j];
        soff = o;
    }
    __syncthreads();
    int* st = isI ? g_startI : g_startU;
    int* cu = isI ? g_curI : g_curU;
    int* cz = isI ? g_cntI : g_cntU;
    int base = (isI ? (b - NB_U) : b) * 1024;
    int v = st[base + t] + soff;
    st[base + t] = v;
    cu[base + t] = v;
    cz[base + t] = 0;      // leave counts zeroed for the next call
    if (b == 0 && t == 0) { g_startU[U_N] = E; g_startI[I_N] = E; }
}

// ---------------- CSR: fill adjacency (u16 payloads) ----------------
__global__ void fill_kernel(const int* __restrict__ src, const int* __restrict__ dst, int E) {
    int e = blockIdx.x * blockDim.x + threadIdx.x;
    if (e >= E) return;
    int s = __ldg(src + e), d = __ldg(dst + e);
    g_adjU[atomicAdd(&g_curU[s], 1)] = (u16)d;
    g_adjI[atomicAdd(&g_curI[d], 1)] = (u16)s;
}

// ---------------- gather-mean inner loop (4-wide, u16 indices) ----------
__device__ __forceinline__ float2 gather_mean(const u16* __restrict__ adj,
                                              const float2* __restrict__ feat,
                                              int s, int e, int lane) {
    float2 a0 = {0.f, 0.f}, a1 = {0.f, 0.f}, a2 = {0.f, 0.f}, a3 = {0.f, 0.f};
    int p = s;
    for (; p + 4 <= e; p += 4) {
        int n0 = __ldg(adj + p), n1 = __ldg(adj + p + 1);
        int n2 = __ldg(adj + p + 2), n3 = __ldg(adj + p + 3);
        float2 v0 = __ldg(feat + (size_t)n0 * 32 + lane);
        float2 v1 = __ldg(feat + (size_t)n1 * 32 + lane);
        float2 v2 = __ldg(feat + (size_t)n2 * 32 + lane);
        float2 v3 = __ldg(feat + (size_t)n3 * 32 + lane);
        a0.x += v0.x; a0.y += v0.y;
        a1.x += v1.x; a1.y += v1.y;
        a2.x += v2.x; a2.y += v2.y;
        a3.x += v3.x; a3.y += v3.y;
    }
    for (; p < e; p++) {
        int n0 = __ldg(adj + p);
        float2 v = __ldg(feat + (size_t)n0 * 32 + lane);
        a0.x += v.x; a0.y += v.y;
    }
    float inv = (e > s) ? 1.0f / (float)(e - s) : 0.0f;
    float2 r;
    r.x = ((a0.x + a1.x) + (a2.x + a3.x)) * inv;
    r.y = ((a0.y + a1.y) + (a2.y + a3.y)) * inv;
    return r;
}

// ---------------- layer-1: pure gather-mean, both directions fused (512 thr) ----------
__global__ void __launch_bounds__(512) gather_kernel(
        const float2* __restrict__ fu, const float2* __restrict__ fi,
        float2* __restrict__ outU, float2* __restrict__ outI) {
    int w = blockIdx.x * 16 + (threadIdx.x >> 5);
    int lane = threadIdx.x & 31;
    const u16* adj; const int* start; const float2* feat; float2* out; int node;
    if (w < I_N) { node = w;        adj = g_adjI; start = g_startI; feat = fu; out = outI; }
    else         { node = w - I_N;  adj = g_adjU; start = g_startU; feat = fi; out = outU; }
    int s = __ldg(start + node), e = __ldg(start + node + 1);
    out[(size_t)node * 32 + lane] = gather_mean(adj, feat, s, e, lane);
}

// ---------------- layer-2 gather + fused layer attention (512 thr) ----------
// isUser=1: grid covers users (writes hu); isUser=0: items (writes hi).
__global__ void __launch_bounds__(512) gather_attn_kernel(
        const float2* __restrict__ ue, const float2* __restrict__ ie, int isUser) {
    int node = blockIdx.x * 16 + (threadIdx.x >> 5);
    int lane = threadIdx.x & 31;
    const u16* adj; const int* start; const float2 *feat, *t0, *t1; float2* out;
    if (!isUser) {  // item node: aggregate L1u, attn over [ie, L1i, L2i]
        adj = g_adjI; start = g_startI;
        feat = (const float2*)g_L1u; t0 = ie; t1 = (const float2*)g_L1i;
        out = (float2*)g_hi;
    } else {        // user node: aggregate L1i, attn over [ue, L1u, L2u]
        adj = g_adjU; start = g_startU;
        feat = (const float2*)g_L1i; t0 = ue; t1 = (const float2*)g_L1u;
        out = (float2*)g_hu;
    }
    int s = __ldg(start + node), e = __ldg(start + node + 1);
    float2 x2 = gather_mean(adj, feat, s, e, lane);
    // fused layer attention
    float2 wv = *((const float2*)g_wa + lane);
    float2 x0 = __ldg(t0 + (size_t)node * 32 + lane);
    float2 x1 = __ldg(t1 + (size_t)node * 32 + lane);
    float s0 = x0.x * wv.x + x0.y * wv.y;
    float s1 = x1.x * wv.x + x1.y * wv.y;
    float s2 = x2.x * wv.x + x2.y * wv.y;
    for (int o = 16; o; o >>= 1) {
        s0 += __shfl_xor_sync(~0u, s0, o);
        s1 += __shfl_xor_sync(~0u, s1, o);
        s2 += __shfl_xor_sync(~0u, s2, o);
    }
    float mm = fmaxf(s0, fmaxf(s1, s2));
    float e0 = __expf(s0 - mm), e1 = __expf(s1 - mm), e2 = __expf(s2 - mm);
    float isum = 1.0f / (e0 + e1 + e2);
    float2 r;
    r.x = (e0 * x0.x + e1 * x1.x + e2 * x2.x) * isum;
    r.y = (e0 * x0.y + e1 * x1.y + e2 * x2.y) * isum;
    out[(size_t)node * 32 + lane] = r;
}

// ---------------- precompute wa = W@a, v1 = WU@aU[:64], v2 = WU@aU[64:], circulant taps ----
__global__ void precompute_kernel(const float* __restrict__ W, const float* __restrict__ a,
                                  const float* __restrict__ WU, const float* __restrict__ aU,
                                  const float* __restrict__ cw) {
    int d = threadIdx.x;   // 64 threads
    if (d >= 64) return;
    float swa = 0.f, sv1 = 0.f, sv2 = 0.f;
    for (int e = 0; e < 64; e++) {
        swa += W[d * 64 + e] * a[e];
        float wue = WU[d * 64 + e];
        sv1 += wue * aU[e];
        sv2 += wue * aU[64 + e];
    }
    g_wa[d] = swa; g_v1[d] = sv1; g_v2[d] = sv2;
    float wr[5], wi[5];
    for (int f = 0; f < 5; f++) { wr[f] = cw[f * 128 + d * 2]; wi[f] = cw[f * 128 + d * 2 + 1]; }
    for (int m = 0; m < 8; m++) {
        float acc = wr[0] + ((m & 1) ? -wr[4] : wr[4]);
        for (int f = 1; f < 4; f++) {
            float x = (float)(f * m) * 0.25f;
            acc += 2.0f * (wr[f] * cospif(x) - wi[f] * sinpif(x));
        }
        g_circ[m * 64 + d] = acc * 0.125f;
    }
}

// ---------------- anchor user embedding: circulant filter + attention + @WU ----------------
__global__ void __launch_bounds__(256) anchor_kernel(const float* __restrict__ ue,
                                                     const float* __restrict__ WU,
                                                     const int* __restrict__ nbr) {
    __shared__ float wus[4096];
    __shared__ float zsh[8][64];
    for (int i = threadIdx.x; i < 4096; i += 256) wus[i] = __ldg(WU + i);
    int lane = threadIdx.x & 31, wid = threadIdx.x >> 5;
    float2 c[8];
#pragma unroll
    for (int m = 0; m < 8; m++) c[m] = *((const float2*)(g_circ + m * 64) + lane);
    float2 v1 = *((const float2*)g_v1 + lane);
    float2 v2 = *((const float2*)g_v2 + lane);
    __syncthreads();

    for (int it = 0; it < 4; it++) {
        int u = blockIdx.x * 32 + it * 8 + wid;
        float2 xv[8];
#pragma unroll
        for (int j = 0; j < 8; j++) {
            int nb = __ldg(nbr + (size_t)u * 8 + j);
            xv[j] = __ldg((const float2*)(ue + (size_t)nb * 64) + lane);
        }
        float2 s[8];
#pragma unroll
        for (int k = 0; k < 8; k++) {
            float sx = 0.f, sy = 0.f;
#pragma unroll
            for (int j = 0; j < 8; j++) {
                float2 cm = c[(k - j) & 7];
                sx += xv[j].x * cm.x;
                sy += xv[j].y * cm.y;
            }
            s[k].x = sx; s[k].y = sy;
        }
        float2 uv = __ldg((const float2*)(ue + (size_t)u * 64) + lane);
        float q = uv.x * v2.x + uv.y * v2.y;
        for (int o = 16; o; o >>= 1) q += __shfl_xor_sync(~0u, q, o);

        float e[8];
#pragma unroll
        for (int k = 0; k < 8; k++) {
            float p = s[k].x * v1.x + s[k].y * v1.y;
            for (int o = 16; o; o >>= 1) p += __shfl_xor_sync(~0u, p, o);
            float t = p + q;
            e[k] = t > 0.f ? t : 0.1f * t;      // LeakyReLU(0.1)
        }
        float mx = e[0];
#pragma unroll
        for (int k = 1; k < 8; k++) mx = fmaxf(mx, e[k]);
        float es = 0.f;
#pragma unroll
        for (int k = 0; k < 8; k++) { e[k] = __expf(e[k] - mx); es += e[k]; }
        float inv = 1.0f / es;
        float2 z = {0.f, 0.f};
#pragma unroll
        for (int k = 0; k < 8; k++) {
            float al = e[k] * inv;
            z.x += al * s[k].x;
            z.y += al * s[k].y;
        }
        zsh[wid][2 * lane]     = z.x;
        zsh[wid][2 * lane + 1] = z.y;
        __syncwarp();
        float2 acc = {0.f, 0.f};
#pragma unroll 8
        for (int d = 0; d < 64; d++) {
            float zd = zsh[wid][d];
            float2 w = *(const float2*)(wus + d * 64 + 2 * lane);
            acc.x += zd * w.x;
            acc.y += zd * w.y;
        }
        ((float2*)(g_anchor + (size_t)u * 64))[lane] = acc;
        __syncwarp();
    }
}

// ---------------- contrastive loss via tf32 mma: 1 block (512 thr) per chunk -------------
// sim = 5c/(na*nc+eps) computed as 5c*t*(1-g+g^2-g^3), t=ir_a*ir_c, g=eps*t; the poly
// correction is applied only in the anchor x anchor quadrant (g >= ~1e-4 only there).
// Last block folds the 200 partials into the final loss (self-resetting ticket).
__global__ void __launch_bounds__(512) contrast_mma_kernel(float* __restrict__ loss_dst) {
    extern __shared__ float sm[];
    u32* Y = (u32*)sm;
    float* inr = sm + 512 * RS2;     // inverse norms
    float* red = inr + 512;
    int tid = threadIdx.x, lane = tid & 31, wid = tid >> 5;
    int chunk = blockIdx.x;
    const float2* r1 = (const float2*)(g_hu     + (size_t)chunk * 256 * 64);
    const float2* r2 = (const float2*)(g_anchor + (size_t)chunk * 256 * 64);

    for (int r = wid * 32; r < wid * 32 + 32; r++) {
        const float2* srcp = (r < 256) ? (r1 + (size_t)r * 32) : (r2 + (size_t)(r - 256) * 32);
        float2 v = __ldg(srcp + lane);
        u32 t0, t1;
        asm("cvt.rna.tf32.f32 %0, %1;" : "=r"(t0) : "f"(v.x));
        asm("cvt.rna.tf32.f32 %0, %1;" : "=r"(t1) : "f"(v.y));
        u64 packed = (u64)t0 | ((u64)t1 << 32);
        *(u64*)(Y + r * RS2 + 2 * lane) = packed;   // single STS.64 (8B-aligned)
        float sq = v.x * v.x + v.y * v.y;
        for (int o = 16; o; o >>= 1) sq += __shfl_xor_sync(~0u, sq, o);
        if (lane == 0) inr[r] = rsqrtf(sq);
    }
    __syncthreads();

    int tig = lane & 3;        // thread-in-group
    int gid = lane >> 2;       // 0..7

    int r0a = wid * 16 + gid, r0b = r0a + 8;            // hu-half rows
    int r1a = 256 + wid * 16 + gid, r1b = r1a + 8;      // anchor-half rows
    u32 A0[8][4], A1[8][4];
#pragma unroll
    for (int s = 0; s < 8; s++) {
        A0[s][0] = Y[r0a * RS2 + 8 * s + tig];
        A0[s][1] = Y[r0b * RS2 + 8 * s + tig];
        A0[s][2] = Y[r0a * RS2 + 8 * s + tig + 4];
        A0[s][3] = Y[r0b * RS2 + 8 * s + tig + 4];
        A1[s][0] = Y[r1a * RS2 + 8 * s + tig];
        A1[s][1] = Y[r1b * RS2 + 8 * s + tig];
        A1[s][2] = Y[r1a * RS2 + 8 * s + tig + 4];
        A1[s][3] = Y[r1b * RS2 + 8 * s + tig + 4];
    }
    float i0a = inr[r0a], i0b = inr[r0b];
    float i1a = inr[r1a], i1b = inr[r1b];
    float ss0a = 0.f, ss0b = 0.f, ss1a = 0.f, ss1b = 0.f;
    float lb0a = 0.f, lb0b = 0.f, lb1a = 0.f, lb1b = 0.f;
    int l0a = r0a ^ 256, l0b = r0b ^ 256, l1a = r1a ^ 256, l1b = r1b ^ 256;

    for (int nt = 0; nt < 64; nt++) {
        float c00 = 0.f, c01 = 0.f, c02 = 0.f, c03 = 0.f;
        float c10 = 0.f, c11 = 0.f, c12 = 0.f, c13 = 0.f;
        int yrow = nt * 8 + gid;
#pragma unroll
        for (int s = 0; s < 8; s++) {
            u32 b0 = Y[yrow * RS2 + 8 * s + tig];
            u32 b1 = Y[yrow * RS2 + 8 * s + tig + 4];
            asm volatile(
                "mma.sync.aligned.m16n8k8.row.col.f32.tf32.tf32.f32 "
                "{%0,%1,%2,%3}, {%4,%5,%6,%7}, {%8,%9}, {%0,%1,%2,%3};"
                : "+f"(c00), "+f"(c01), "+f"(c02), "+f"(c03)
                : "r"(A0[s][0]), "r"(A0[s][1]), "r"(A0[s][2]), "r"(A0[s][3]),
                  "r"(b0), "r"(b1));
            asm volatile(
                "mma.sync.aligned.m16n8k8.row.col.f32.tf32.tf32.f32 "
                "{%0,%1,%2,%3}, {%4,%5,%6,%7}, {%8,%9}, {%0,%1,%2,%3};"
                : "+f"(c10), "+f"(c11), "+f"(c12), "+f"(c13)
                : "r"(A1[s][0]), "r"(A1[s][1]), "r"(A1[s][2]), "r"(A1[s][3]),
                  "r"(b0), "r"(b1));
        }
        int ca = nt * 8 + 2 * tig, cb = ca + 1;
        float ia = inr[ca], ib = inr[cb];
        float t00 = i0a * ia, t01 = i0a * ib;
        float t02 = i0b * ia, t03 = i0b * ib;
        float t10 = i1a * ia, t11 = i1a * ib;
        float t12 = i1b * ia, t13 = i1b * ib;
        float s00 = 5.f * c00 * t00, s01 = 5.f * c01 * t01;
        float s02 = 5.f * c02 * t02, s03 = 5.f * c03 * t03;
        float s10 = 5.f * c10 * t10, s11 = 5.f * c11 * t11;
        float s12 = 5.f * c12 * t12, s13 = 5.f * c13 * t13;
        if (nt >= 32) {   // anchor x anchor quadrant: exact epsilon correction
            float g10 = 1e-6f * t10, g11 = 1e-6f * t11;
            float g12 = 1e-6f * t12, g13 = 1e-6f * t13;
            s10 *= 1.f - g10 * (1.f - g10 * (1.f - g10));
            s11 *= 1.f - g11 * (1.f - g11 * (1.f - g11));
            s12 *= 1.f - g12 * (1.f - g12 * (1.f - g12));
            s13 *= 1.f - g13 * (1.f - g13 * (1.f - g13));
        }
        ss0a += ((ca == r0a) ? 0.f : __expf(s00 - 5.f)) + ((cb == r0a) ? 0.f : __expf(s01 - 5.f));
        ss0b += ((ca == r0b) ? 0.f : __expf(s02 - 5.f)) + ((cb == r0b) ? 0.f : __expf(s03 - 5.f));
        ss1a += ((ca == r1a) ? 0.f : __expf(s10 - 5.f)) + ((cb == r1a) ? 0.f : __expf(s11 - 5.f));
        ss1b += ((ca == r1b) ? 0.f : __expf(s12 - 5.f)) + ((cb == r1b) ? 0.f : __expf(s13 - 5.f));
        if (ca == l0a) lb0a = s00;
        if (cb == l0a) lb0a = s01;
        if (ca == l0b) lb0b = s02;
        if (cb == l0b) lb0b = s03;
        if (ca == l1a) lb1a = s10;
        if (cb == l1a) lb1a = s11;
        if (ca == l1b) lb1b = s12;
        if (cb == l1b) lb1b = s13;
    }
#pragma unroll
    for (int o = 1; o <= 2; o <<= 1) {
        ss0a += __shfl_xor_sync(~0u, ss0a, o);
        ss0b += __shfl_xor_sync(~0u, ss0b, o);
        ss1a += __shfl_xor_sync(~0u, ss1a, o);
        ss1b += __shfl_xor_sync(~0u, ss1b, o);
        lb0a += __shfl_xor_sync(~0u, lb0a, o);
        lb0b += __shfl_xor_sync(~0u, lb0b, o);
        lb1a += __shfl_xor_sync(~0u, lb1a, o);
        lb1b += __shfl_xor_sync(~0u, lb1b, o);
    }
    float myloss = 0.f;
    if (tig == 0) {
        myloss = (5.f + __logf(ss0a) - lb0a) + (5.f + __logf(ss0b) - lb0b) +
                 (5.f + __logf(ss1a) - lb1a) + (5.f + __logf(ss1b) - lb1b);
    }
    red[tid] = myloss;
    __syncthreads();
    for (int s = 256; s; s >>= 1) {
        if (tid < s) red[tid] += red[tid + s];
        __syncthreads();
    }
    if (tid == 0) g_partial[chunk] = red[0];

    // ---- last block folds partials into the final loss ----
    __threadfence();
    __shared__ int isLast;
    if (tid == 0) isLast = (atomicAdd(&g_ticket, 1) == NCH - 1);
    __syncthreads();
    if (isLast) {
        float v = (tid < NCH) ? __ldcg(&g_partial[tid]) : 0.0f;
        red[tid] = v;
        __syncthreads();
        for (int s = 256; s; s >>= 1) {
            if (tid < s) red[tid] += red[tid + s];
            __syncthreads();
        }
        if (tid == 0) {
            *loss_dst = red[0] / (float)(NCH * 512);
            g_ticket = 0;   // self-reset for next call / replay
        }
    }
}

// ---------------- pos/neg scores ----------------
__global__ void score_kernel(const int* __restrict__ pu, const int* __restrict__ pi,
                             const int* __restrict__ nu, const int* __restrict__ ni,
                             float* __restrict__ out, int EP) {
    int t = blockIdx.x * blockDim.x + threadIdx.x;
    if (t >= EP) return;
    {
        const float4* a = (const float4*)(g_hu + (size_t)__ldg(pu + t) * 64);
        const float4* b = (const float4*)(g_hi + (size_t)__ldg(pi + t) * 64);
        float s = 0.f;
#pragma unroll
        for (int i = 0; i < 16; i++) {
            float4 xx = __ldg(a + i), yy = __ldg(b + i);
            s += xx.x * yy.x + xx.y * yy.y + xx.z * yy.z + xx.w * yy.w;
        }
        out[t] = s;
    }
    {
        const float4* a = (const float4*)(g_hu + (size_t)__ldg(nu + t) * 64);
        const float4* b = (const float4*)(g_hi + (size_t)__ldg(ni + t) * 64);
        float s = 0.f;
#pragma unroll
        for (int i = 0; i < 16; i++) {
            float4 xx = __ldg(a + i), yy = __ldg(b + i);
            s += xx.x * yy.x + xx.y * yy.y + xx.z * yy.z + xx.w * yy.w;
        }
        out[EP + t] = s;
    }
}

// ---------------- launch ----------------
extern "C" void kernel_launch(void* const* d_in, const int* in_sizes, int n_in,
                              void* d_out, int out_size) {
    const float* user_emb = (const float*)d_in[0];
    const float* item_emb = (const float*)d_in[1];
    const float* W        = (const float*)d_in[2];
    const float* a        = (const float*)d_in[3];
    const float* WU       = (const float*)d_in[4];
    const float* aU       = (const float*)d_in[5];
    const float* cw       = (const float*)d_in[6];
    const int*   rate_src = (const int*)d_in[7];
    const int*   rate_dst = (const int*)d_in[8];
    const int*   pos_u    = (const int*)d_in[9];
    const int*   pos_i    = (const int*)d_in[10];
    const int*   neg_u    = (const int*)d_in[11];
    const int*   neg_i    = (const int*)d_in[12];
    const int*   nbr      = (const int*)d_in[13];
    float* out = (float*)d_out;

    const int E  = in_sizes[7];
    const int EP = in_sizes[9];

    float *L1u, *L1i;
    cudaGetSymbolAddress((void**)&L1u, g_L1u);
    cudaGetSymbolAddress((void**)&L1i, g_L1i);

    const int CSMEM = (512 * RS2 + 512 + 512) * (int)sizeof(float);
    static cudaStream_t s2 = nullptr;
    static cudaEvent_t evFork = nullptr, evPre = nullptr, evAnchor = nullptr;
    static cudaEvent_t evG1 = nullptr, evHu = nullptr, evScore = nullptr;
    if (!s2) {
        cudaFuncSetAttribute(contrast_mma_kernel,
                             cudaFuncAttributeMaxDynamicSharedMemorySize, CSMEM);
        cudaStreamCreateWithFlags(&s2, cudaStreamNonBlocking);
        cudaEventCreateWithFlags(&evFork, cudaEventDisableTiming);
        cudaEventCreateWithFlags(&evPre, cudaEventDisableTiming);
        cudaEventCreateWithFlags(&evAnchor, cudaEventDisableTiming);
        cudaEventCreateWithFlags(&evG1, cudaEventDisableTiming);
        cudaEventCreateWithFlags(&evHu, cudaEventDisableTiming);
        cudaEventCreateWithFlags(&evScore, cudaEventDisableTiming);
    }

    // ---- fork: anchor path on side stream ----
    cudaEventRecord(evFork, 0);
    cudaStreamWaitEvent(s2, evFork, 0);
    precompute_kernel<<<1, 64, 0, s2>>>(W, a, WU, aU, cw);
    cudaEventRecord(evPre, s2);
    anchor_kernel<<<U_N / 32, 256, 0, s2>>>(user_emb, WU, nbr);
    cudaEventRecord(evAnchor, s2);

    // ---- main path: CSR build + propagation (counters pre-zeroed; scanC re-zeros) ----
    count_kernel<<<(E + 255) / 256, 256>>>(rate_src, rate_dst, E);
    scanA_kernel<<<NB_T, 1024>>>();
    scanC_kernel<<<NB_T, 1024>>>(E);
    fill_kernel<<<(E + 255) / 256, 256>>>(rate_src, rate_dst, E);

    int ggrid = (I_N + U_N) / 16;
    gather_kernel<<<ggrid, 512>>>((const float2*)user_emb, (const float2*)item_emb,
                                  (float2*)L1u, (float2*)L1i);
    cudaEventRecord(evG1, 0);

    cudaStreamWaitEvent(0, evPre, 0);   // fused attn needs g_wa
    gather_attn_kernel<<<U_N / 16, 512>>>((const float2*)user_emb,
                                          (const float2*)item_emb, 1);   // users -> hu
    cudaEventRecord(evHu, 0);

    // ---- side stream: items part of gather_attn + score, concurrent with contrast ----
    cudaStreamWaitEvent(s2, evG1, 0);
    gather_attn_kernel<<<I_N / 16, 512, 0, s2>>>((const float2*)user_emb,
                                                 (const float2*)item_emb, 0);  // items -> hi
    cudaStreamWaitEvent(s2, evHu, 0);   // score needs hu too
    score_kernel<<<(EP + 255) / 256, 256, 0, s2>>>(pos_u, pos_i, neg_u, neg_i, out, EP);
    cudaEventRecord(evScore, s2);

    // ---- main: contrast (incl. final fold) ----
    cudaStreamWaitEvent(0, evAnchor, 0);
    contrast_mma_kernel<<<NCH, 512, CSMEM>>>(out + 2 * (size_t)EP);
    cudaStreamWaitEvent(0, evScore, 0);    // join side stream before capture end
}

// round 17
// speedup vs baseline: 1.0148x; 1.0148x over previous
#include <cuda_runtime.h>
#include <math.h>

// ---------------- fixed problem constants ----------------
#define U_N   51200
#define I_N   25600
#define E_MAX 1000000
#define NCH   200          // U_N / 256 chunks
#define RS2   68           // padded smem row stride (words) for contrast (tf32)
#define NB_U  50           // U_N / 1024
#define NB_I  25           // I_N / 1024
#define NB_T  75

typedef unsigned long long u64;
typedef unsigned int u32;
typedef unsigned short u16;

// ---------------- device scratch (static, no runtime alloc) ----------------
// g_cntU/g_cntI start zero and are re-zeroed by scanC each call; g_ticket self-resets.
__device__ __align__(256) float g_L1u[U_N * 64];
__device__ __align__(256) float g_L1i[I_N * 64];
__device__ __align__(256) float g_hu [U_N * 64];
__device__ __align__(256) float g_hi [I_N * 64];
__device__ __align__(256) float g_anchor[U_N * 64];
__device__ __align__(256) int g_cntU[U_N];
__device__ __align__(256) int g_cntI[I_N];
__device__ __align__(256) int g_startU[U_N + 1];
__device__ __align__(256) int g_startI[I_N + 1];
__device__ __align__(256) int g_curU[U_N];
__device__ __align__(256) int g_curI[I_N];
__device__ __align__(256) u16 g_adjU[E_MAX];   // per user: neighbor items (<25600 fits u16)
__device__ __align__(256) u16 g_adjI[E_MAX];   // per item: neighbor users (<51200 fits u16)
__device__ int g_bsum[NB_T];
__device__ int g_ticket;
__device__ float g_wa[64];
__device__ float g_v1[64];
__device__ float g_v2[64];
__device__ float g_circ[8 * 64];          // [tap m][d]
__device__ float g_partial[NCH];          // per-chunk contrast partials

// ---------------- CSR: count ----------------
__global__ void count_kernel(const int* __restrict__ src, const int* __restrict__ dst, int E) {
    int e = blockIdx.x * blockDim.x + threadIdx.x;
    if (e >= E) return;
    atomicAdd(&g_cntU[__ldg(src + e)], 1);
    atomicAdd(&g_cntI[__ldg(dst + e)], 1);
}

// ---------------- CSR scan stage A: block-local exclusive scan ----------------
__global__ void __launch_bounds__(1024) scanA_kernel() {
    int b = blockIdx.x;
    int isI = (b >= NB_U);
    const int* c = isI ? g_cntI : g_cntU;
    int* st = isI ? g_startI : g_startU;
    int base = (isI ? (b - NB_U) : b) * 1024;
    int t = threadIdx.x, lane = t & 31, wid = t >> 5;
    __shared__ int ws[32];
    int v = c[base + t];
    int x = v;
#pragma unroll
    for (int o = 1; o < 32; o <<= 1) {
        int y = __shfl_up_sync(~0u, x, o);
        if (lane >= o) x += y;
    }
    if (lane == 31) ws[wid] = x;
    __syncthreads();
    if (wid == 0) {
        int s = ws[lane];
#pragma unroll
        for (int o = 1; o < 32; o <<= 1) {
            int y = __shfl_up_sync(~0u, s, o);
            if (lane >= o) s += y;
        }
        ws[lane] = s;
    }
    __syncthreads();
    int incl = x + (wid ? ws[wid - 1] : 0);
    st[base + t] = incl - v;
    if (t == 1023) g_bsum[b] = incl;
}

// ---------------- CSR scan stage C: segment offsets (from bsum) + cursors + re-zero ----
__global__ void __launch_bounds__(1024) scanC_kernel(int E) {
    __shared__ int sb[NB_T];
    __shared__ int soff;
    int b = blockIdx.x, t = threadIdx.x;
    if (t < NB_T) sb[t] = g_bsum[t];
    __syncthreads();
    int isI = (b >= NB_U);
    int seg0 = isI ? NB_U : 0;
    if (t == 0) {
        int o = 0;
        for (int j = seg0; j < b; j++) o += sb[j];
        soff = o;
    }
    __syncthreads();
    int* st = isI ? g_startI : g_startU;
    int* cu = isI ? g_curI : g_curU;
    int* cz = isI ? g_cntI : g_cntU;
    int base = (isI ? (b - NB_U) : b) * 1024;
    int v = st[base + t] + soff;
    st[base + t] = v;
    cu[base + t] = v;
    cz[base + t] = 0;      // leave counts zeroed for the next call
    if (b == 0 && t == 0) { g_startU[U_N] = E; g_startI[I_N] = E; }
}

// ---------------- CSR: fill adjacency (u16 payloads) ----------------
__global__ void fill_kernel(const int* __restrict__ src, const int* __restrict__ dst, int E) {
    int e = blockIdx.x * blockDim.x + threadIdx.x;
    if (e >= E) return;
    int s = __ldg(src + e), d = __ldg(dst + e);
    g_adjU[atomicAdd(&g_curU[s], 1)] = (u16)d;
    g_adjI[atomicAdd(&g_curI[d], 1)] = (u16)s;
}

// ---------------- gather-mean inner loop (4-wide, u16 indices) ----------
__device__ __forceinline__ float2 gather_mean(const u16* __restrict__ adj,
                                              const float2* __restrict__ feat,
                                              int s, int e, int lane) {
    float2 a0 = {0.f, 0.f}, a1 = {0.f, 0.f}, a2 = {0.f, 0.f}, a3 = {0.f, 0.f};
    int p = s;
    for (; p + 4 <= e; p += 4) {
        int n0 = __ldg(adj + p), n1 = __ldg(adj + p + 1);
        int n2 = __ldg(adj + p + 2), n3 = __ldg(adj + p + 3);
        float2 v0 = __ldg(feat + (size_t)n0 * 32 + lane);
        float2 v1 = __ldg(feat + (size_t)n1 * 32 + lane);
        float2 v2 = __ldg(feat + (size_t)n2 * 32 + lane);
        float2 v3 = __ldg(feat + (size_t)n3 * 32 + lane);
        a0.x += v0.x; a0.y += v0.y;
        a1.x += v1.x; a1.y += v1.y;
        a2.x += v2.x; a2.y += v2.y;
        a3.x += v3.x; a3.y += v3.y;
    }
    for (; p < e; p++) {
        int n0 = __ldg(adj + p);
        float2 v = __ldg(feat + (size_t)n0 * 32 + lane);
        a0.x += v.x; a0.y += v.y;
    }
    float inv = (e > s) ? 1.0f / (float)(e - s) : 0.0f;
    float2 r;
    r.x = ((a0.x + a1.x) + (a2.x + a3.x)) * inv;
    r.y = ((a0.y + a1.y) + (a2.y + a3.y)) * inv;
    return r;
}

// ---------------- layer-1: pure gather-mean, both directions fused ----------------
__global__ void __launch_bounds__(256) gather_kernel(
        const float2* __restrict__ fu, const float2* __restrict__ fi,
        float2* __restrict__ outU, float2* __restrict__ outI) {
    int w = blockIdx.x * 8 + (threadIdx.x >> 5);
    int lane = threadIdx.x & 31;
    const u16* adj; const int* start; const float2* feat; float2* out; int node;
    if (w < I_N) { node = w;        adj = g_adjI; start = g_startI; feat = fu; out = outI; }
    else         { node = w - I_N;  adj = g_adjU; start = g_startU; feat = fi; out = outU; }
    int s = __ldg(start + node), e = __ldg(start + node + 1);
    out[(size_t)node * 32 + lane] = gather_mean(adj, feat, s, e, lane);
}

// ---------------- layer-2 gather + fused layer attention -> writes h directly ----------
// isUser=1: grid covers users (writes hu); isUser=0: items (writes hi).
__global__ void __launch_bounds__(256) gather_attn_kernel(
        const float2* __restrict__ ue, const float2* __restrict__ ie, int isUser) {
    int node = blockIdx.x * 8 + (threadIdx.x >> 5);
    int lane = threadIdx.x & 31;
    const u16* adj; const int* start; const float2 *feat, *t0, *t1; float2* out;
    if (!isUser) {  // item node: aggregate L1u, attn over [ie, L1i, L2i]
        adj = g_adjI; start = g_startI;
        feat = (const float2*)g_L1u; t0 = ie; t1 = (const float2*)g_L1i;
        out = (float2*)g_hi;
    } else {        // user node: aggregate L1i, attn over [ue, L1u, L2u]
        adj = g_adjU; start = g_startU;
        feat = (const float2*)g_L1i; t0 = ue; t1 = (const float2*)g_L1u;
        out = (float2*)g_hu;
    }
    int s = __ldg(start + node), e = __ldg(start + node + 1);
    float2 x2 = gather_mean(adj, feat, s, e, lane);
    // fused layer attention
    float2 wv = *((const float2*)g_wa + lane);
    float2 x0 = __ldg(t0 + (size_t)node * 32 + lane);
    float2 x1 = __ldg(t1 + (size_t)node * 32 + lane);
    float s0 = x0.x * wv.x + x0.y * wv.y;
    float s1 = x1.x * wv.x + x1.y * wv.y;
    float s2 = x2.x * wv.x + x2.y * wv.y;
    for (int o = 16; o; o >>= 1) {
        s0 += __shfl_xor_sync(~0u, s0, o);
        s1 += __shfl_xor_sync(~0u, s1, o);
        s2 += __shfl_xor_sync(~0u, s2, o);
    }
    float mm = fmaxf(s0, fmaxf(s1, s2));
    float e0 = __expf(s0 - mm), e1 = __expf(s1 - mm), e2 = __expf(s2 - mm);
    float isum = 1.0f / (e0 + e1 + e2);
    float2 r;
    r.x = (e0 * x0.x + e1 * x1.x + e2 * x2.x) * isum;
    r.y = (e0 * x0.y + e1 * x1.y + e2 * x2.y) * isum;
    out[(size_t)node * 32 + lane] = r;
}

// ---------------- precompute wa = W@a, v1 = WU@aU[:64], v2 = WU@aU[64:], circulant taps ----
__global__ void precompute_kernel(const float* __restrict__ W, const float* __restrict__ a,
                                  const float* __restrict__ WU, const float* __restrict__ aU,
                                  const float* __restrict__ cw) {
    int d = threadIdx.x;   // 64 threads
    if (d >= 64) return;
    float swa = 0.f, sv1 = 0.f, sv2 = 0.f;
    for (int e = 0; e < 64; e++) {
        swa += W[d * 64 + e] * a[e];
        float wue = WU[d * 64 + e];
        sv1 += wue * aU[e];
        sv2 += wue * aU[64 + e];
    }
    g_wa[d] = swa; g_v1[d] = sv1; g_v2[d] = sv2;
    float wr[5], wi[5];
    for (int f = 0; f < 5; f++) { wr[f] = cw[f * 128 + d * 2]; wi[f] = cw[f * 128 + d * 2 + 1]; }
    for (int m = 0; m < 8; m++) {
        float acc = wr[0] + ((m & 1) ? -wr[4] : wr[4]);
        for (int f = 1; f < 4; f++) {
            float x = (float)(f * m) * 0.25f;
            acc += 2.0f * (wr[f] * cospif(x) - wi[f] * sinpif(x));
        }
        g_circ[m * 64 + d] = acc * 0.125f;
    }
}

// ---------------- anchor user embedding: circulant filter + attention + @WU ----------------
__global__ void __launch_bounds__(256) anchor_kernel(const float* __restrict__ ue,
                                                     const float* __restrict__ WU,
                                                     const int* __restrict__ nbr) {
    __shared__ float wus[4096];
    __shared__ float zsh[8][64];
    for (int i = threadIdx.x; i < 4096; i += 256) wus[i] = __ldg(WU + i);
    int lane = threadIdx.x & 31, wid = threadIdx.x >> 5;
    float2 c[8];
#pragma unroll
    for (int m = 0; m < 8; m++) c[m] = *((const float2*)(g_circ + m * 64) + lane);
    float2 v1 = *((const float2*)g_v1 + lane);
    float2 v2 = *((const float2*)g_v2 + lane);
    __syncthreads();

    for (int it = 0; it < 4; it++) {
        int u = blockIdx.x * 32 + it * 8 + wid;
        float2 xv[8];
#pragma unroll
        for (int j = 0; j < 8; j++) {
            int nb = __ldg(nbr + (size_t)u * 8 + j);
            xv[j] = __ldg((const float2*)(ue + (size_t)nb * 64) + lane);
        }
        float2 s[8];
#pragma unroll
        for (int k = 0; k < 8; k++) {
            float sx = 0.f, sy = 0.f;
#pragma unroll
            for (int j = 0; j < 8; j++) {
                float2 cm = c[(k - j) & 7];
                sx += xv[j].x * cm.x;
                sy += xv[j].y * cm.y;
            }
            s[k].x = sx; s[k].y = sy;
        }
        float2 uv = __ldg((const float2*)(ue + (size_t)u * 64) + lane);
        float q = uv.x * v2.x + uv.y * v2.y;
        for (int o = 16; o; o >>= 1) q += __shfl_xor_sync(~0u, q, o);

        float e[8];
#pragma unroll
        for (int k = 0; k < 8; k++) {
            float p = s[k].x * v1.x + s[k].y * v1.y;
            for (int o = 16; o; o >>= 1) p += __shfl_xor_sync(~0u, p, o);
            float t = p + q;
            e[k] = t > 0.f ? t : 0.1f * t;      // LeakyReLU(0.1)
        }
        float mx = e[0];
#pragma unroll
        for (int k = 1; k < 8; k++) mx = fmaxf(mx, e[k]);
        float es = 0.f;
#pragma unroll
        for (int k = 0; k < 8; k++) { e[k] = __expf(e[k] - mx); es += e[k]; }
        float inv = 1.0f / es;
        float2 z = {0.f, 0.f};
#pragma unroll
        for (int k = 0; k < 8; k++) {
            float al = e[k] * inv;
            z.x += al * s[k].x;
            z.y += al * s[k].y;
        }
        zsh[wid][2 * lane]     = z.x;
        zsh[wid][2 * lane + 1] = z.y;
        __syncwarp();
        float2 acc = {0.f, 0.f};
#pragma unroll 8
        for (int d = 0; d < 64; d++) {
            float zd = zsh[wid][d];
            float2 w = *(const float2*)(wus + d * 64 + 2 * lane);
            acc.x += zd * w.x;
            acc.y += zd * w.y;
        }
        ((float2*)(g_anchor + (size_t)u * 64))[lane] = acc;
        __syncwarp();
    }
}

// ---------------- contrastive loss via tf32 mma: 1 block (512 thr) per chunk -------------
// sim = 5c/(na*nc+eps) computed as 5c*t*(1-g+g^2-g^3), t=ir_a*ir_c, g=eps*t; the poly
// correction is applied only in the anchor x anchor quadrant (g >= ~1e-4 only there).
// Last block folds the 200 partials into the final loss (self-resetting ticket).
__global__ void __launch_bounds__(512) contrast_mma_kernel(float* __restrict__ loss_dst) {
    extern __shared__ float sm[];
    u32* Y = (u32*)sm;
    float* inr = sm + 512 * RS2;     // inverse norms
    float* red = inr + 512;
    int tid = threadIdx.x, lane = tid & 31, wid = tid >> 5;
    int chunk = blockIdx.x;
    const float2* r1 = (const float2*)(g_hu     + (size_t)chunk * 256 * 64);
    const float2* r2 = (const float2*)(g_anchor + (size_t)chunk * 256 * 64);

    for (int r = wid * 32; r < wid * 32 + 32; r++) {
        const float2* srcp = (r < 256) ? (r1 + (size_t)r * 32) : (r2 + (size_t)(r - 256) * 32);
        float2 v = __ldg(srcp + lane);
        u32 t0, t1;
        asm("cvt.rna.tf32.f32 %0, %1;" : "=r"(t0) : "f"(v.x));
        asm("cvt.rna.tf32.f32 %0, %1;" : "=r"(t1) : "f"(v.y));
        u64 packed = (u64)t0 | ((u64)t1 << 32);
        *(u64*)(Y + r * RS2 + 2 * lane) = packed;   // single STS.64 (8B-aligned)
        float sq = v.x * v.x + v.y * v.y;
        for (int o = 16; o; o >>= 1) sq += __shfl_xor_sync(~0u, sq, o);
        if (lane == 0) inr[r] = rsqrtf(sq);
    }
    __syncthreads();

    int tig = lane & 3;        // thread-in-group
    int gid = lane >> 2;       // 0..7

    int r0a = wid * 16 + gid, r0b = r0a + 8;            // hu-half rows
    int r1a = 256 + wid * 16 + gid, r1b = r1a + 8;      // anchor-half rows
    u32 A0[8][4], A1[8][4];
#pragma unroll
    for (int s = 0; s < 8; s++) {
        A0[s][0] = Y[r0a * RS2 + 8 * s + tig];
        A0[s][1] = Y[r0b * RS2 + 8 * s + tig];
        A0[s][2] = Y[r0a * RS2 + 8 * s + tig + 4];
        A0[s][3] = Y[r0b * RS2 + 8 * s + tig + 4];
        A1[s][0] = Y[r1a * RS2 + 8 * s + tig];
        A1[s][1] = Y[r1b * RS2 + 8 * s + tig];
        A1[s][2] = Y[r1a * RS2 + 8 * s + tig + 4];
        A1[s][3] = Y[r1b * RS2 + 8 * s + tig + 4];
    }
    float i0a = inr[r0a], i0b = inr[r0b];
    float i1a = inr[r1a], i1b = inr[r1b];
    float ss0a = 0.f, ss0b = 0.f, ss1a = 0.f, ss1b = 0.f;
    float lb0a = 0.f, lb0b = 0.f, lb1a = 0.f, lb1b = 0.f;
    int l0a = r0a ^ 256, l0b = r0b ^ 256, l1a = r1a ^ 256, l1b = r1b ^ 256;

    for (int nt = 0; nt < 64; nt++) {
        float c00 = 0.f, c01 = 0.f, c02 = 0.f, c03 = 0.f;
        float c10 = 0.f, c11 = 0.f, c12 = 0.f, c13 = 0.f;
        int yrow = nt * 8 + gid;
#pragma unroll
        for (int s = 0; s < 8; s++) {
            u32 b0 = Y[yrow * RS2 + 8 * s + tig];
            u32 b1 = Y[yrow * RS2 + 8 * s + tig + 4];
            asm volatile(
                "mma.sync.aligned.m16n8k8.row.col.f32.tf32.tf32.f32 "
                "{%0,%1,%2,%3}, {%4,%5,%6,%7}, {%8,%9}, {%0,%1,%2,%3};"
                : "+f"(c00), "+f"(c01), "+f"(c02), "+f"(c03)
                : "r"(A0[s][0]), "r"(A0[s][1]), "r"(A0[s][2]), "r"(A0[s][3]),
                  "r"(b0), "r"(b1));
            asm volatile(
                "mma.sync.aligned.m16n8k8.row.col.f32.tf32.tf32.f32 "
                "{%0,%1,%2,%3}, {%4,%5,%6,%7}, {%8,%9}, {%0,%1,%2,%3};"
                : "+f"(c10), "+f"(c11), "+f"(c12), "+f"(c13)
                : "r"(A1[s][0]), "r"(A1[s][1]), "r"(A1[s][2]), "r"(A1[s][3]),
                  "r"(b0), "r"(b1));
        }
        int ca = nt * 8 + 2 * tig, cb = ca + 1;
        float ia = inr[ca], ib = inr[cb];
        float t00 = i0a * ia, t01 = i0a * ib;
        float t02 = i0b * ia, t03 = i0b * ib;
        float t10 = i1a * ia, t11 = i1a * ib;
        float t12 = i1b * ia, t13 = i1b * ib;
        float s00 = 5.f * c00 * t00, s01 = 5.f * c01 * t01;
        float s02 = 5.f * c02 * t02, s03 = 5.f * c03 * t03;
        float s10 = 5.f * c10 * t10, s11 = 5.f * c11 * t11;
        float s12 = 5.f * c12 * t12, s13 = 5.f * c13 * t13;
        if (nt >= 32) {   // anchor x anchor quadrant: exact epsilon correction
            float g10 = 1e-6f * t10, g11 = 1e-6f * t11;
            float g12 = 1e-6f * t12, g13 = 1e-6f * t13;
            s10 *= 1.f - g10 * (1.f - g10 * (1.f - g10));
            s11 *= 1.f - g11 * (1.f - g11 * (1.f - g11));
            s12 *= 1.f - g12 * (1.f - g12 * (1.f - g12));
            s13 *= 1.f - g13 * (1.f - g13 * (1.f - g13));
        }
        ss0a += ((ca == r0a) ? 0.f : __expf(s00 - 5.f)) + ((cb == r0a) ? 0.f : __expf(s01 - 5.f));
        ss0b += ((ca == r0b) ? 0.f : __expf(s02 - 5.f)) + ((cb == r0b) ? 0.f : __expf(s03 - 5.f));
        ss1a += ((ca == r1a) ? 0.f : __expf(s10 - 5.f)) + ((cb == r1a) ? 0.f : __expf(s11 - 5.f));
        ss1b += ((ca == r1b) ? 0.f : __expf(s12 - 5.f)) + ((cb == r1b) ? 0.f : __expf(s13 - 5.f));
        if (ca == l0a) lb0a = s00;
        if (cb == l0a) lb0a = s01;
        if (ca == l0b) lb0b = s02;
        if (cb == l0b) lb0b = s03;
        if (ca == l1a) lb1a = s10;
        if (cb == l1a) lb1a = s11;
        if (ca == l1b) lb1b = s12;
        if (cb == l1b) lb1b = s13;
    }
#pragma unroll
    for (int o = 1; o <= 2; o <<= 1) {
        ss0a += __shfl_xor_sync(~0u, ss0a, o);
        ss0b += __shfl_xor_sync(~0u, ss0b, o);
        ss1a += __shfl_xor_sync(~0u, ss1a, o);
        ss1b += __shfl_xor_sync(~0u, ss1b, o);
        lb0a += __shfl_xor_sync(~0u, lb0a, o);
        lb0b += __shfl_xor_sync(~0u, lb0b, o);
        lb1a += __shfl_xor_sync(~0u, lb1a, o);
        lb1b += __shfl_xor_sync(~0u, lb1b, o);
    }
    float myloss = 0.f;
    if (tig == 0) {
        myloss = (5.f + __logf(ss0a) - lb0a) + (5.f + __logf(ss0b) - lb0b) +
                 (5.f + __logf(ss1a) - lb1a) + (5.f + __logf(ss1b) - lb1b);
    }
    red[tid] = myloss;
    __syncthreads();
    for (int s = 256; s; s >>= 1) {
        if (tid < s) red[tid] += red[tid + s];
        __syncthreads();
    }
    if (tid == 0) g_partial[chunk] = red[0];

    // ---- last block folds partials into the final loss ----
    __threadfence();
    __shared__ int isLast;
    if (tid == 0) isLast = (atomicAdd(&g_ticket, 1) == NCH - 1);
    __syncthreads();
    if (isLast) {
        float v = (tid < NCH) ? __ldcg(&g_partial[tid]) : 0.0f;
        red[tid] = v;
        __syncthreads();
        for (int s = 256; s; s >>= 1) {
            if (tid < s) red[tid] += red[tid + s];
            __syncthreads();
        }
        if (tid == 0) {
            *loss_dst = red[0] / (float)(NCH * 512);
            g_ticket = 0;   // self-reset for next call / replay
        }
    }
}

// ---------------- pos/neg scores ----------------
__global__ void score_kernel(const int* __restrict__ pu, const int* __restrict__ pi,
                             const int* __restrict__ nu, const int* __restrict__ ni,
                             float* __restrict__ out, int EP) {
    int t = blockIdx.x * blockDim.x + threadIdx.x;
    if (t >= EP) return;
    {
        const float4* a = (const float4*)(g_hu + (size_t)__ldg(pu + t) * 64);
        const float4* b = (const float4*)(g_hi + (size_t)__ldg(pi + t) * 64);
        float s = 0.f;
#pragma unroll
        for (int i = 0; i < 16; i++) {
            float4 xx = __ldg(a + i), yy = __ldg(b + i);
            s += xx.x * yy.x + xx.y * yy.y + xx.z * yy.z + xx.w * yy.w;
        }
        out[t] = s;
    }
    {
        const float4* a = (const float4*)(g_hu + (size_t)__ldg(nu + t) * 64);
        const float4* b = (const float4*)(g_hi + (size_t)__ldg(ni + t) * 64);
        float s = 0.f;
#pragma unroll
        for (int i = 0; i < 16; i++) {
            float4 xx = __ldg(a + i), yy = __ldg(b + i);
            s += xx.x * yy.x + xx.y * yy.y + xx.z * yy.z + xx.w * yy.w;
        }
        out[EP + t] = s;
    }
}

// ---------------- launch ----------------
extern "C" void kernel_launch(void* const* d_in, const int* in_sizes, int n_in,
                              void* d_out, int out_size) {
    const float* user_emb = (const float*)d_in[0];
    const float* item_emb = (const float*)d_in[1];
    const float* W        = (const float*)d_in[2];
    const float* a        = (const float*)d_in[3];
    const float* WU       = (const float*)d_in[4];
    const float* aU       = (const float*)d_in[5];
    const float* cw       = (const float*)d_in[6];
    const int*   rate_src = (const int*)d_in[7];
    const int*   rate_dst = (const int*)d_in[8];
    const int*   pos_u    = (const int*)d_in[9];
    const int*   pos_i    = (const int*)d_in[10];
    const int*   neg_u    = (const int*)d_in[11];
    const int*   neg_i    = (const int*)d_in[12];
    const int*   nbr      = (const int*)d_in[13];
    float* out = (float*)d_out;

    const int E  = in_sizes[7];
    const int EP = in_sizes[9];

    float *L1u, *L1i;
    cudaGetSymbolAddress((void**)&L1u, g_L1u);
    cudaGetSymbolAddress((void**)&L1i, g_L1i);

    const int CSMEM = (512 * RS2 + 512 + 512) * (int)sizeof(float);
    static cudaStream_t s2 = nullptr;
    static cudaEvent_t evFork = nullptr, evPre = nullptr, evAnchor = nullptr;
    static cudaEvent_t evG1 = nullptr, evHu = nullptr, evScore = nullptr;
    if (!s2) {
        cudaFuncSetAttribute(contrast_mma_kernel,
                             cudaFuncAttributeMaxDynamicSharedMemorySize, CSMEM);
        cudaStreamCreateWithFlags(&s2, cudaStreamNonBlocking);
        cudaEventCreateWithFlags(&evFork, cudaEventDisableTiming);
        cudaEventCreateWithFlags(&evPre, cudaEventDisableTiming);
        cudaEventCreateWithFlags(&evAnchor, cudaEventDisableTiming);
        cudaEventCreateWithFlags(&evG1, cudaEventDisableTiming);
        cudaEventCreateWithFlags(&evHu, cudaEventDisableTiming);
        cudaEventCreateWithFlags(&evScore, cudaEventDisableTiming);
    }

    // ---- fork: anchor path on side stream ----
    cudaEventRecord(evFork, 0);
    cudaStreamWaitEvent(s2, evFork, 0);
    precompute_kernel<<<1, 64, 0, s2>>>(W, a, WU, aU, cw);
    cudaEventRecord(evPre, s2);
    anchor_kernel<<<U_N / 32, 256, 0, s2>>>(user_emb, WU, nbr);
    cudaEventRecord(evAnchor, s2);

    // ---- main path: CSR build + propagation (counters pre-zeroed; scanC re-zeros) ----
    count_kernel<<<(E + 255) / 256, 256>>>(rate_src, rate_dst, E);
    scanA_kernel<<<NB_T, 1024>>>();
    scanC_kernel<<<NB_T, 1024>>>(E);
    fill_kernel<<<(E + 255) / 256, 256>>>(rate_src, rate_dst, E);

    int ggrid = (I_N + U_N) / 8;
    gather_kernel<<<ggrid, 256>>>((const float2*)user_emb, (const float2*)item_emb,
                                  (float2*)L1u, (float2*)L1i);
    cudaEventRecord(evG1, 0);

    cudaStreamWaitEvent(0, evPre, 0);   // fused attn needs g_wa
    gather_attn_kernel<<<U_N / 8, 256>>>((const float2*)user_emb,
                                         (const float2*)item_emb, 1);   // users -> hu
    cudaEventRecord(evHu, 0);

    // ---- side stream: items part of gather_attn + score, concurrent with contrast ----
    cudaStreamWaitEvent(s2, evG1, 0);
    gather_attn_kernel<<<I_N / 8, 256, 0, s2>>>((const float2*)user_emb,
                                                (const float2*)item_emb, 0);  // items -> hi
    cudaStreamWaitEvent(s2, evHu, 0);   // score needs hu too
    score_kernel<<<(EP + 255) / 256, 256, 0, s2>>>(pos_u, pos_i, neg_u, neg_i, out, EP);
    cudaEventRecord(evScore, s2);

    // ---- main: contrast (incl. final fold) ----
    cudaStreamWaitEvent(0, evAnchor, 0);
    contrast_mma_kernel<<<NCH, 512, CSMEM>>>(out + 2 * (size_t)EP);
    cudaStreamWaitEvent(0, evScore, 0);    // join side stream before capture end
}